// round 1
// baseline (speedup 1.0000x reference)
#include <cuda_runtime.h>
#include <math.h>

// ---------------- problem constants (fixed shapes) ----------------
// x: [8,256,96,96], means: [1,128,64], w_match: [64,256,3,3], b_match: [64]
// w_asm: [256,256,1,1], b_asm: [256]
// L = 9216, WINDOW = 144, n_win = 64, pad = 0, R = 1
//
// d_out layout (tuple concat, all f32):
//   out    [8,256,96,96]          @ 0          (18,874,368)
//   score  [8,1,64,144,432]       @ 18,874,368 (31,850,496)
//   bs     [8,1,9216]             @ 50,724,864 (73,728)
//   codes  [8,9216]               @ 50,798,592 (73,728)

#define NB   8
#define CIN  256
#define LTOK 9216
#define CQ   64
#define NCL  128
#define WIN  144
#define NWIN 64
#define WX3  432

// ---------------- device scratch (allocation-free rule: device globals) ----
__device__ float g_xembed[NB*LTOK*CQ];     // conv3x3 out, token-major
__device__ float g_yembed[NB*LTOK*CIN];    // conv1x1 out, token-major
__device__ int   g_buckets[NB*LTOK];
__device__ int   g_counts[NB*NCL];
__device__ int   g_offs[NB*NCL];
__device__ int   g_idx[NB*LTOK];           // sorted pos -> token
__device__ int   g_undo[NB*LTOK];          // token -> sorted pos
__device__ float g_xs[NB*LTOK*CQ];         // sorted x_embed (unnormalized)
__device__ float g_xmn[NB*LTOK*CQ];        // sorted x_embed l2-normalized (eps 5e-5)
__device__ float g_ys[NB*LTOK*CIN];        // sorted y_embed
__device__ float g_rets[NB*LTOK*CIN];      // attention output, sorted order

// ---------------- conv 3x3 (implicit GEMM, one (row,batch) per block) ------
__global__ __launch_bounds__(256) void k_conv3x3(const float* __restrict__ x,
                                                 const float* __restrict__ w,
                                                 const float* __restrict__ b) {
    __shared__ float in_s[8][3][100];   // 8 ch x 3 rows x cols(-1..96)
    __shared__ float w_s[8][9][64];
    int h = blockIdx.x, n = blockIdx.y;
    int tid = threadIdx.x;
    int cq = tid & 63, pg = tid >> 6;   // 4 groups x 24 positions
    float bias = b[cq];
    float acc[24];
#pragma unroll
    for (int p = 0; p < 24; p++) acc[p] = bias;

    for (int cc = 0; cc < 32; cc++) {   // 32 chunks of 8 input channels
        for (int i = tid; i < 8*3*98; i += 256) {
            int cl = i / 294, r = i % 294, kh = r / 98, col = r % 98;
            int hh = h + kh - 1, ww = col - 1;
            float v = 0.f;
            if (hh >= 0 && hh < 96 && ww >= 0 && ww < 96)
                v = x[((n*CIN + cc*8 + cl)*96 + hh)*96 + ww];
            in_s[cl][kh][col] = v;
        }
        for (int i = tid; i < 8*9*64; i += 256) {
            int cl = i / 576, r = i % 576, tap = r / 64, q = r & 63;
            w_s[cl][tap][q] = w[(q*CIN + cc*8 + cl)*9 + tap];
        }
        __syncthreads();
#pragma unroll
        for (int cl = 0; cl < 8; cl++) {
#pragma unroll
            for (int kh = 0; kh < 3; kh++) {
                float vin[26];
#pragma unroll
                for (int u = 0; u < 26; u++) vin[u] = in_s[cl][kh][pg*24 + u];
                float w0 = w_s[cl][kh*3+0][cq];
                float w1 = w_s[cl][kh*3+1][cq];
                float w2 = w_s[cl][kh*3+2][cq];
#pragma unroll
                for (int p = 0; p < 24; p++)
                    acc[p] += vin[p]*w0 + vin[p+1]*w1 + vin[p+2]*w2;
            }
        }
        __syncthreads();
    }
    int lbase = h*96 + pg*24;
#pragma unroll
    for (int p = 0; p < 24; p++)
        g_xembed[(n*LTOK + lbase + p)*CQ + cq] = acc[p];
}

// ---------------- conv 1x1 (GEMM: 9216x256x256 per batch) -----------------
__global__ __launch_bounds__(256) void k_conv1x1(const float* __restrict__ x,
                                                 const float* __restrict__ w,
                                                 const float* __restrict__ b) {
    __shared__ float x_s[32][128];
    __shared__ float w_s[32][64];
    int l0 = blockIdx.x * 128, co0 = blockIdx.y * 64, n = blockIdx.z;
    int tid = threadIdx.x, ty = tid >> 4, tx = tid & 15;
    float acc[8][4] = {};
    for (int kc = 0; kc < 8; kc++) {
        for (int i = tid; i < 32*128; i += 256) {
            int k = i >> 7, p = i & 127;
            x_s[k][p] = x[(n*CIN + kc*32 + k)*LTOK + l0 + p];
        }
        for (int i = tid; i < 32*64; i += 256) {
            int k = i >> 6, j = i & 63;
            w_s[k][j] = w[(co0 + j)*CIN + kc*32 + k];
        }
        __syncthreads();
#pragma unroll
        for (int k = 0; k < 32; k++) {
            float xv[8], wv[4];
#pragma unroll
            for (int u = 0; u < 8; u++) xv[u] = x_s[k][ty + 16*u];
#pragma unroll
            for (int v = 0; v < 4; v++) wv[v] = w_s[k][tx + 16*v];
#pragma unroll
            for (int u = 0; u < 8; u++)
#pragma unroll
                for (int v = 0; v < 4; v++) acc[u][v] += xv[u]*wv[v];
        }
        __syncthreads();
    }
#pragma unroll
    for (int u = 0; u < 8; u++)
#pragma unroll
        for (int v = 0; v < 4; v++)
            g_yembed[(n*LTOK + l0 + ty + 16*u)*CIN + co0 + tx + 16*v] =
                acc[u][v] + b[co0 + tx + 16*v];
}

// ---------------- bucket assignment: argmax_k (x . mean_k) ------------------
// (positive per-token normalization cannot change the argmax or tie order)
__global__ __launch_bounds__(128) void k_assign(const float* __restrict__ means,
                                                float* __restrict__ codes_out) {
    __shared__ float x_s[128][65];
    __shared__ float m_s[32][64];
    int n = blockIdx.y, t0 = blockIdx.x * 128, tid = threadIdx.x;
    for (int i = tid; i < 128*64; i += 128) {
        int r = i >> 6, c = i & 63;
        x_s[r][c] = g_xembed[(n*LTOK + t0 + r)*CQ + c];
    }
    __syncthreads();
    float best = -INFINITY; int bk = 0;
    for (int kc = 0; kc < 4; kc++) {
        for (int i = tid; i < 32*64; i += 128) {
            int k = i >> 6, c = i & 63;
            m_s[k][c] = means[(kc*32 + k)*64 + c];
        }
        __syncthreads();
#pragma unroll
        for (int kg = 0; kg < 4; kg++) {
            float accv[8] = {};
            for (int c = 0; c < 64; c++) {
                float xv = x_s[tid][c];
#pragma unroll
                for (int e = 0; e < 8; e++) accv[e] += xv * m_s[kg*8+e][c];
            }
#pragma unroll
            for (int e = 0; e < 8; e++) {
                int k = kc*32 + kg*8 + e;
                if (accv[e] > best) { best = accv[e]; bk = k; }  // strict > = first-idx tie
            }
        }
        __syncthreads();
    }
    g_buckets[n*LTOK + t0 + tid] = bk;
    codes_out[n*LTOK + t0 + tid] = (float)bk;
}

// ---------------- stable counting sort ------------------------------------
__global__ void k_histzero() {
    int i = blockIdx.x*256 + threadIdx.x;
    if (i < NB*NCL) g_counts[i] = 0;
}
__global__ void k_hist() {
    int i = blockIdx.x*256 + threadIdx.x;  // 73728 threads
    atomicAdd(&g_counts[(i/LTOK)*NCL + g_buckets[i]], 1);
}
__global__ void k_scan() {
    int n = blockIdx.x;
    if (threadIdx.x == 0) {
        int run = 0;
        for (int b2 = 0; b2 < NCL; b2++) { g_offs[n*NCL + b2] = run; run += g_counts[n*NCL + b2]; }
    }
}
// one warp per (batch,bucket): ballot-scan gives stable placement
__global__ __launch_bounds__(256) void k_place() {
    int g = blockIdx.x*8 + (threadIdx.x >> 5);
    int n = g >> 7, bkt = g & 127, lane = threadIdx.x & 31;
    int start = g_offs[n*NCL + bkt];
    int cnt = 0;
    const int* bk = &g_buckets[n*LTOK];
    for (int t0 = 0; t0 < LTOK; t0 += 32) {
        int t = t0 + lane;
        bool match = (bk[t] == bkt);
        unsigned m = __ballot_sync(0xffffffffu, match);
        if (match) {
            int pos = start + cnt + __popc(m & ((1u << lane) - 1u));
            g_idx[n*LTOK + pos] = t;
            g_undo[n*LTOK + t] = pos;
        }
        cnt += __popc(m);
    }
}

// ---------------- gather sorted xs / normalized xs / ys ---------------------
__global__ __launch_bounds__(256) void k_gather() {
    int n = blockIdx.y;
    int s = blockIdx.x*8 + (threadIdx.x >> 5);
    int lane = threadIdx.x & 31;
    int t = g_idx[n*LTOK + s];
    const float* xe = &g_xembed[(n*LTOK + t)*CQ];
    float v0 = xe[lane], v1 = xe[lane + 32];
    float* xs = &g_xs[(n*LTOK + s)*CQ];
    xs[lane] = v0; xs[lane + 32] = v1;
    float ss = v0*v0 + v1*v1;
#pragma unroll
    for (int o = 16; o > 0; o >>= 1) ss += __shfl_xor_sync(0xffffffffu, ss, o);
    float inv = 1.f / fmaxf(sqrtf(ss), 5e-5f);
    float* xm = &g_xmn[(n*LTOK + s)*CQ];
    xm[lane] = v0*inv; xm[lane + 32] = v1*inv;
    const float* ye = &g_yembed[(n*LTOK + t)*CIN];
    float* ys = &g_ys[(n*LTOK + s)*CIN];
#pragma unroll
    for (int q = 0; q < 8; q++) ys[lane + 32*q] = ye[lane + 32*q];
}

// ---------------- raw = xb @ xmatch^T, one (win, seg) tile per block -------
__global__ __launch_bounds__(256) void k_raw(float* __restrict__ score) {
    extern __shared__ float sm[];
    float* A = sm;                 // [144][69] sorted unnormalized
    float* B = sm + 144*69;        // [144][69] neighbor window normalized
    int win = blockIdx.x, seg = blockIdx.y, n = blockIdx.z;
    int w2 = (seg == 0) ? win : (seg == 1) ? ((win + 63) & 63) : ((win + 1) & 63);
    int tid = threadIdx.x;
    for (int i = tid; i < 144*64; i += 256) {
        int r = i >> 6, k = i & 63;
        A[r*69 + k] = g_xs [(n*LTOK + win*WIN + r)*CQ + k];
        B[r*69 + k] = g_xmn[(n*LTOK + w2 *WIN + r)*CQ + k];
    }
    __syncthreads();
    int ty = tid >> 4, tx = tid & 15;
    float acc[9][9] = {};
#pragma unroll 2
    for (int k = 0; k < 64; k++) {
        float av[9], bv[9];
#pragma unroll
        for (int u = 0; u < 9; u++) av[u] = A[(ty + 16*u)*69 + k];
#pragma unroll
        for (int v = 0; v < 9; v++) bv[v] = B[(tx + 16*v)*69 + k];
#pragma unroll
        for (int u = 0; u < 9; u++)
#pragma unroll
            for (int v = 0; v < 9; v++) acc[u][v] += av[u]*bv[v];
    }
    size_t base = (size_t)(n*NWIN + win) * WIN * WX3;
#pragma unroll
    for (int u = 0; u < 9; u++)
#pragma unroll
        for (int v = 0; v < 9; v++)
            score[base + (size_t)(ty + 16*u)*WX3 + seg*WIN + tx + 16*v] = acc[u][v];
}

// ---------------- logsumexp + exp in place, one warp per row ---------------
__global__ __launch_bounds__(256) void k_lse(float* __restrict__ score,
                                             float* __restrict__ bsout) {
    int r = blockIdx.x*8 + (threadIdx.x >> 5);   // r in [0, 73728)
    int lane = threadIdx.x & 31;
    float* p = score + (size_t)r * WX3;
    float v[14];
#pragma unroll
    for (int q = 0; q < 14; q++) {
        int j = q*32 + lane;
        v[q] = (j < WX3) ? p[j] : -INFINITY;
    }
    float m = -INFINITY;
#pragma unroll
    for (int q = 0; q < 14; q++) m = fmaxf(m, v[q]);
#pragma unroll
    for (int o = 16; o > 0; o >>= 1) m = fmaxf(m, __shfl_xor_sync(0xffffffffu, m, o));
    float s = 0.f;
#pragma unroll
    for (int q = 0; q < 14; q++) s += expf(v[q] - m);   // exp(-inf)=0 handles tail
#pragma unroll
    for (int o = 16; o > 0; o >>= 1) s += __shfl_xor_sync(0xffffffffu, s, o);
    float bs = m + logf(s);
#pragma unroll
    for (int q = 0; q < 14; q++) {
        int j = q*32 + lane;
        if (j < WX3) p[j] = expf(v[q] - bs);
    }
    if (lane == 0) bsout[r] = bs;
}

// ---------------- ret = score @ y3 (144x432 @ 432x128 per block) -----------
__global__ __launch_bounds__(256) void k_ret(const float* __restrict__ score) {
    __shared__ float s_s[36][145];
    __shared__ float y_s[36][128];
    int cot = blockIdx.x, win = blockIdx.y, n = blockIdx.z;
    int tid = threadIdx.x, ty = tid >> 4, tx = tid & 15;
    float acc[9][8] = {};
    for (int kc = 0; kc < 12; kc++) {
        int seg = kc >> 2;
        int w2 = (seg == 0) ? win : (seg == 1) ? ((win + 63) & 63) : ((win + 1) & 63);
        int jb = (kc & 3) * 36;
        for (int i = tid; i < 144*36; i += 256) {
            int r = i / 36, c = i % 36;
            s_s[c][r] = score[((size_t)(n*LTOK + win*WIN + r))*WX3 + kc*36 + c];
        }
        for (int i = tid; i < 36*128; i += 256) {
            int k = i >> 7, j = i & 127;
            y_s[k][j] = g_ys[(n*LTOK + w2*WIN + jb + k)*CIN + cot*128 + j];
        }
        __syncthreads();
#pragma unroll 2
        for (int k = 0; k < 36; k++) {
            float sv[9], yv[8];
#pragma unroll
            for (int u = 0; u < 9; u++) sv[u] = s_s[k][ty + 16*u];
#pragma unroll
            for (int v = 0; v < 8; v++) yv[v] = y_s[k][tx + 16*v];
#pragma unroll
            for (int u = 0; u < 9; u++)
#pragma unroll
                for (int v = 0; v < 8; v++) acc[u][v] += sv[u]*yv[v];
        }
        __syncthreads();
    }
#pragma unroll
    for (int u = 0; u < 9; u++)
#pragma unroll
        for (int v = 0; v < 8; v++)
            g_rets[(n*LTOK + win*WIN + ty + 16*u)*CIN + cot*128 + tx + 16*v] = acc[u][v];
}

// ---------------- unsort + residual, coalesced via smem transpose ----------
__global__ __launch_bounds__(256) void k_scatter(const float* __restrict__ x,
                                                 float* __restrict__ out) {
    __shared__ float tile[32][257];
    __shared__ int srow[32];
    int n = blockIdx.y, t0 = blockIdx.x * 32, tid = threadIdx.x;
    if (tid < 32) srow[tid] = g_undo[n*LTOK + t0 + tid];
    __syncthreads();
    for (int i = tid; i < 32*256; i += 256) {
        int tt = i >> 8, co = i & 255;
        tile[tt][co] = g_rets[(n*LTOK + srow[tt])*CIN + co];
    }
    __syncthreads();
    for (int i = tid; i < 32*256; i += 256) {
        int co = i >> 5, tt = i & 31;
        size_t gi = ((size_t)(n*CIN + co))*LTOK + t0 + tt;
        out[gi] = tile[tt][co]*0.1f + x[gi];
    }
}

// ---------------- launch ----------------------------------------------------
extern "C" void kernel_launch(void* const* d_in, const int* in_sizes, int n_in,
                              void* d_out, int out_size) {
    const float* x       = (const float*)d_in[0];
    const float* means   = (const float*)d_in[1];
    const float* w_match = (const float*)d_in[2];
    const float* b_match = (const float*)d_in[3];
    const float* w_asm   = (const float*)d_in[4];
    const float* b_asm   = (const float*)d_in[5];
    float* out   = (float*)d_out;
    float* score = out + 18874368;        // [8,1,64,144,432]
    float* bs    = out + 50724864;        // [8,1,9216]
    float* codes = out + 50798592;        // [8,9216]

    cudaFuncSetAttribute(k_raw, cudaFuncAttributeMaxDynamicSharedMemorySize, 2*144*69*4);

    k_conv3x3<<<dim3(96, 8), 256>>>(x, w_match, b_match);
    k_conv1x1<<<dim3(72, 4, 8), 256>>>(x, w_asm, b_asm);
    k_assign<<<dim3(72, 8), 128>>>(means, codes);
    k_histzero<<<4, 256>>>();
    k_hist<<<288, 256>>>();
    k_scan<<<8, 32>>>();
    k_place<<<128, 256>>>();
    k_gather<<<dim3(1152, 8), 256>>>();
    k_raw<<<dim3(64, 3, 8), 256, 2*144*69*4>>>(score);
    k_lse<<<9216, 256>>>(score, bs);
    k_ret<<<dim3(2, 64, 8), 256>>>(score);
    k_scatter<<<dim3(288, 8), 256>>>(x, out);
}